// round 16
// baseline (speedup 1.0000x reference)
#include <cuda_runtime.h>
#include <math.h>

// Problem constants
#define TT    1024
#define DIMX  1024
#define HH    8
#define DK    192
#define DV    128
#define QLR   768
#define KVLR  512
#define DROPE 64

#define NBIG 2944
#define CC   16            // chunk length
#define NCH  (TT / CC)     // 64 chunks

// ---------------- scratch ----------------
__device__ float d_bc  [DIMX * NBIG];
__device__ float d_big [TT * NBIG];
__device__ float d_qn  [TT * QLR];
__device__ float d_kvn [TT * KVLR];
__device__ float d_q   [TT * HH * DK];
__device__ float d_kv  [TT * HH * 256];
__device__ float d_kf  [TT * HH * DK];
__device__ float d_ov  [TT * HH * DV];
// chunked-recurrence scratch
__device__ float d_wch [NCH * HH * CC * DK];   // w = k .* a
__device__ float d_kch [NCH * HH * CC * DK];   // kappa = k ./ a
__device__ float d_qch [NCH * HH * CC * DK];   // qt = q .* a
__device__ float d_a16 [NCH * HH * DK];        // a at chunk end
__device__ float d_Nm  [NCH * HH * CC * CC];   // (I + B Mstrict)^-1 B
__device__ float d_Gm  [NCH * HH * CC * CC];   // tril(qt kappa^T)

// ================= TF32 tensor-core GEMM (double-buffered, cp.async B) =================
#define BM 64
#define BN 128
#define BK 16

__device__ __forceinline__ unsigned f2tf(float f) {
    unsigned u;
    asm("cvt.rna.tf32.f32 %0, %1;" : "=r"(u) : "f"(f));
    return u;
}

__device__ __forceinline__ void mma_tf32(float* c, const unsigned* a, const unsigned* b) {
    asm volatile(
        "mma.sync.aligned.m16n8k8.row.col.f32.tf32.tf32.f32 "
        "{%0,%1,%2,%3}, {%4,%5,%6,%7}, {%8,%9}, {%0,%1,%2,%3};\n"
        : "+f"(c[0]), "+f"(c[1]), "+f"(c[2]), "+f"(c[3])
        : "r"(a[0]), "r"(a[1]), "r"(a[2]), "r"(a[3]), "r"(b[0]), "r"(b[1]));
}

__device__ __forceinline__ void cp16(float* dst, const float* src) {
    unsigned s = (unsigned)__cvta_generic_to_shared(dst);
    asm volatile("cp.async.ca.shared.global [%0], [%1], 16;\n" :: "r"(s), "l"(src));
}
#define CP_COMMIT() asm volatile("cp.async.commit_group;\n" ::: "memory")
#define CP_WAIT0()  asm volatile("cp.async.wait_group 0;\n" ::: "memory")

__device__ __forceinline__ float epi1(float v, int gc, const float* __restrict__ bias) {
    if (gc >= 1344 && gc < 2888) {
        float b = (gc < 2880) ? bias[gc - 1344] : 0.f;
        v = 1.f / (1.f + expf(-(v + b)));
    }
    return v;
}

template <int EPI>
__device__ __forceinline__ void tgemm_core(int N, int K,
                                           const float* __restrict__ A, int lda,
                                           const float* __restrict__ B, int ldb,
                                           const float* __restrict__ bias,
                                           float* __restrict__ C, int ldc,
                                           float* sA, float* sB) {
    const int tid  = threadIdx.x;
    const int crow = blockIdx.y * BM;
    const int ccol = blockIdx.x * BN;

    const int wid  = tid >> 5;
    const int lane = tid & 31;
    const int lq   = lane >> 2;
    const int lr   = lane & 3;
    const int rm   = (wid & 1) * 32;
    const int cn   = (wid >> 1) * 32;

    const int am  = tid >> 2;
    const int ak4 = (tid & 3) * 4;
    const int bk  = tid >> 4;
    const int bc8 = (tid & 15) * 8;
    const int swb = (((bk & 3) ^ ((bk >> 2) & 3)) << 3);

    float acc[2][4][4] = {};
    float4 aR;

    aR = *reinterpret_cast<const float4*>(&A[(long)(crow + am) * lda + ak4]);
    cp16(&sB[bk * BN + ((bc8) ^ swb)],     &B[(long)bk * ldb + ccol + bc8]);
    cp16(&sB[bk * BN + ((bc8 + 4) ^ swb)], &B[(long)bk * ldb + ccol + bc8 + 4]);
    CP_COMMIT();
    {
        const float av[4] = {aR.x, aR.y, aR.z, aR.w};
        #pragma unroll
        for (int i = 0; i < 4; ++i) {
            const int k  = ak4 + i;
            const int sw = (((k & 3) ^ ((k >> 2) & 3)) << 3);
            sA[k * BM + (am ^ sw)] = av[i];
        }
    }
    if (K > BK)
        aR = *reinterpret_cast<const float4*>(&A[(long)(crow + am) * lda + BK + ak4]);
    CP_WAIT0();
    __syncthreads();

    int buf = 0;
    for (int k0 = 0; k0 < K; k0 += BK, buf ^= 1) {
        float* cA = sA + buf * (BK * BM);
        float* cB = sB + buf * (BK * BN);
        const int nxt = buf ^ 1;

        if (k0 + BK < K) {
            float* nB = sB + nxt * (BK * BN);
            cp16(&nB[bk * BN + ((bc8) ^ swb)],     &B[(long)(k0 + BK + bk) * ldb + ccol + bc8]);
            cp16(&nB[bk * BN + ((bc8 + 4) ^ swb)], &B[(long)(k0 + BK + bk) * ldb + ccol + bc8 + 4]);
            CP_COMMIT();
            float* nA = sA + nxt * (BK * BM);
            const float av[4] = {aR.x, aR.y, aR.z, aR.w};
            #pragma unroll
            for (int i = 0; i < 4; ++i) {
                const int k  = ak4 + i;
                const int sw = (((k & 3) ^ ((k >> 2) & 3)) << 3);
                nA[k * BM + (am ^ sw)] = av[i];
            }
            if (k0 + 2 * BK < K)
                aR = *reinterpret_cast<const float4*>(&A[(long)(crow + am) * lda + k0 + 2 * BK + ak4]);
        }

        #pragma unroll
        for (int k8 = 0; k8 < BK; k8 += 8) {
            const int f0 = ((lr ^ (k8 >> 2)) & 3) << 3;
            const int f1 = f0 ^ 8;
            unsigned af[2][4], bf[4][2];
            #pragma unroll
            for (int mt = 0; mt < 2; ++mt) {
                const int r = rm + mt * 16 + lq;
                af[mt][0] = f2tf(cA[(k8 + lr) * BM + (r ^ f0)]);
                af[mt][1] = f2tf(cA[(k8 + lr) * BM + ((r + 8) ^ f0)]);
                af[mt][2] = f2tf(cA[(k8 + lr + 4) * BM + (r ^ f1)]);
                af[mt][3] = f2tf(cA[(k8 + lr + 4) * BM + ((r + 8) ^ f1)]);
            }
            #pragma unroll
            for (int nt = 0; nt < 4; ++nt) {
                const int c = cn + nt * 8 + lq;
                bf[nt][0] = f2tf(cB[(k8 + lr) * BN + (c ^ f0)]);
                bf[nt][1] = f2tf(cB[(k8 + lr + 4) * BN + (c ^ f1)]);
            }
            #pragma unroll
            for (int mt = 0; mt < 2; ++mt)
                #pragma unroll
                for (int nt = 0; nt < 4; ++nt)
                    mma_tf32(acc[mt][nt], af[mt], bf[nt]);
        }
        CP_WAIT0();
        __syncthreads();
    }

    #pragma unroll
    for (int mt = 0; mt < 2; ++mt) {
        const int row = crow + rm + mt * 16 + lq;
        #pragma unroll
        for (int nt = 0; nt < 4; ++nt) {
            const int col = ccol + cn + nt * 8 + lr * 2;
            float v0 = acc[mt][nt][0], v1 = acc[mt][nt][1];
            float v2 = acc[mt][nt][2], v3 = acc[mt][nt][3];
            if (EPI == 1) {
                v0 = epi1(v0, col, bias);     v1 = epi1(v1, col + 1, bias);
                v2 = epi1(v2, col, bias);     v3 = epi1(v3, col + 1, bias);
            }
            *reinterpret_cast<float2*>(&C[(long)row * ldc + col])       = make_float2(v0, v1);
            *reinterpret_cast<float2*>(&C[(long)(row + 8) * ldc + col]) = make_float2(v2, v3);
        }
    }
}

template <int EPI>
__global__ __launch_bounds__(256, 2)
void tgemm_kernel(int N, int K, const float* __restrict__ A, int lda,
                  const float* __restrict__ B, int ldb,
                  const float* __restrict__ bias, float* __restrict__ C, int ldc) {
    __shared__ float sA[2 * BK * BM];
    __shared__ float sB[2 * BK * BN];
    tgemm_core<EPI>(N, K, A, lda, B, ldb, bias, C, ldc, sA, sB);
}

__global__ __launch_bounds__(256, 2)
void tgemm_dual_kernel(int N0, int K0, const float* __restrict__ A0,
                       const float* __restrict__ B0, float* __restrict__ C0,
                       int N1, int K1, const float* __restrict__ A1,
                       const float* __restrict__ B1, float* __restrict__ C1) {
    __shared__ float sA[2 * BK * BM];
    __shared__ float sB[2 * BK * BN];
    if (blockIdx.z == 0) {
        if ((int)blockIdx.x * BN >= N0) return;
        tgemm_core<0>(N0, K0, A0, K0, B0, N0, nullptr, C0, N0, sA, sB);
    } else {
        tgemm_core<0>(N1, K1, A1, K1, B1, N1, nullptr, C1, N1, sA, sB);
    }
}

// ---------------- stage-1 weight concat ----------------
__global__ void concat_w(const float* __restrict__ wq_a,
                         const float* __restrict__ wkv_a,
                         const float* __restrict__ wg_w,
                         const float* __restrict__ wb,
                         float* __restrict__ Bc) {
    const int c = blockIdx.x * 128 + threadIdx.x;
    const int r = blockIdx.y;
    float v;
    if      (c < 768)  v = wq_a [r * 768  + c];
    else if (c < 1344) v = wkv_a[r * 576  + (c - 768)];
    else if (c < 2880) v = wg_w [r * 1536 + (c - 1344)];
    else if (c < 2888) v = wb   [r * 8    + (c - 2880)];
    else               v = 0.f;
    Bc[(long)r * NBIG + c] = v;
}

// ---------------- fused row RMS norms ----------------
__device__ __forceinline__ void rms_row(const float* __restrict__ row,
                                        const float* __restrict__ w,
                                        float* __restrict__ out, int n) {
    float ss = 0.f;
    for (int i = threadIdx.x; i < n; i += 256) {
        float v = row[i];
        ss += v * v;
    }
    #pragma unroll
    for (int off = 16; off; off >>= 1)
        ss += __shfl_xor_sync(0xffffffffu, ss, off);
    __shared__ float red[8];
    __shared__ float scale_s;
    const int wid = threadIdx.x >> 5;
    if ((threadIdx.x & 31) == 0) red[wid] = ss;
    __syncthreads();
    if (threadIdx.x == 0) {
        float tot = 0.f;
        #pragma unroll
        for (int i = 0; i < 8; ++i) tot += red[i];
        scale_s = rsqrtf(tot / (float)n + 1e-5f);
    }
    __syncthreads();
    const float sc = scale_s;
    for (int i = threadIdx.x; i < n; i += 256)
        out[i] = row[i] * sc * w[i];
    __syncthreads();
}

__global__ void rms_fused(const float* __restrict__ big,
                          const float* __restrict__ qw,
                          const float* __restrict__ kvw,
                          float* __restrict__ qn,
                          float* __restrict__ kvn) {
    const int t = blockIdx.x;
    rms_row(big + (long)t * NBIG,       qw,  qn  + (long)t * QLR,  QLR);
    rms_row(big + (long)t * NBIG + 768, kvw, kvn + (long)t * KVLR, KVLR);
}

// ---------------- prep: l2norm q/k, assemble k ----------------
__global__ void prep_kernel(float* __restrict__ q,
                            const float* __restrict__ kv,
                            const float* __restrict__ big,
                            float* __restrict__ kf) {
    const int t = blockIdx.x >> 3;
    const int h = blockIdx.x & 7;
    const int i = threadIdx.x;  // 0..191

    const int qidx = t * (HH * DK) + h * DK + i;
    const float qv = q[qidx];
    const float kvv = (i < 128) ? kv[t * (HH * 256) + h * 256 + i]
                                : big[(long)t * NBIG + 1280 + (i - 128)];

    float q2 = qv * qv, k2 = kvv * kvv;
    #pragma unroll
    for (int off = 16; off; off >>= 1) {
        q2 += __shfl_xor_sync(0xffffffffu, q2, off);
        k2 += __shfl_xor_sync(0xffffffffu, k2, off);
    }
    __shared__ float sq[6], sk[6];
    __shared__ float scl[2];
    const int wid = threadIdx.x >> 5;
    if ((threadIdx.x & 31) == 0) { sq[wid] = q2; sk[wid] = k2; }
    __syncthreads();
    if (threadIdx.x == 0) {
        float a = 0.f, b = 0.f;
        #pragma unroll
        for (int j = 0; j < 6; ++j) { a += sq[j]; b += sk[j]; }
        scl[0] = rsqrtf(a + 1e-6f) * 0.07216878364870322f;
        scl[1] = rsqrtf(b + 1e-6f);
    }
    __syncthreads();
    q[qidx] = qv * scl[0];
    kf[qidx] = kvv * scl[1];
}

// ================= chunked KDA: prepass =================
__global__ __launch_bounds__(256)
void chunk_pre(const float* __restrict__ qf,
               const float* __restrict__ kf,
               const float* __restrict__ big,
               float* __restrict__ wg, float* __restrict__ kg,
               float* __restrict__ qg, float* __restrict__ a16g,
               float* __restrict__ Ng, float* __restrict__ Gg) {
    const int ch = blockIdx.x;      // c*8 + h
    const int c  = ch >> 3, h = ch & 7;
    __shared__ float ws[CC][193], ks[CC][193], qs[CC][193];
    __shared__ float ms[CC * CC];
    __shared__ float bs[CC];
    const int tid = threadIdx.x;

    if (tid < 192) {
        const int d = tid;
        float a = 1.f;
        for (int t = 0; t < CC; ++t) {
            const long row = (long)(c * CC + t);
            const float e  = big[row * NBIG + 1344 + h * 192 + d];
            a *= e;
            const float kd = kf[row * 1536 + h * 192 + d];
            const float qd = qf[row * 1536 + h * 192 + d];
            const float w  = kd * a;
            const float ka = kd / a;
            const float qa = qd * a;
            ws[t][d] = w; ks[t][d] = ka; qs[t][d] = qa;
            const long g = ((long)ch * CC + t) * 192 + d;
            wg[g] = w; kg[g] = ka; qg[g] = qa;
        }
        a16g[(long)ch * 192 + d] = a;
    }
    if (tid < CC)
        bs[tid] = big[(long)(c * CC + tid) * NBIG + 2880 + h];
    __syncthreads();

    {
        const int t = tid >> 4, s = tid & 15;
        float m = 0.f, g = 0.f;
        float m1 = 0.f, g1 = 0.f;
        for (int d = 0; d < 192; d += 2) {
            float kd0 = ks[s][d], kd1 = ks[s][d + 1];
            m  = fmaf(ws[t][d],     kd0, m);
            m1 = fmaf(ws[t][d + 1], kd1, m1);
            g  = fmaf(qs[t][d],     kd0, g);
            g1 = fmaf(qs[t][d + 1], kd1, g1);
        }
        m += m1; g += g1;
        ms[tid] = (s < t) ? m : 0.f;
        Gg[(long)ch * 256 + tid] = (s <= t) ? g : 0.f;
    }
    __syncthreads();

    if (tid < 16) {
        const int j = tid;
        float n[CC];
        #pragma unroll
        for (int t = 0; t < CC; ++t) {
            float acc = (t == j) ? 1.f : 0.f;
            #pragma unroll
            for (int s = 0; s < CC; ++s)
                if (s < t) acc = fmaf(-ms[t * 16 + s], n[s], acc);
            n[t] = bs[t] * acc;
        }
        #pragma unroll
        for (int t = 0; t < CC; ++t)
            Ng[(long)ch * 256 + t * 16 + j] = n[t];
    }
}

// ================= chunked KDA: sequential kernel (v3: 512 threads, d-split) =================
// S stored [j][194]. y/o dot split across half=tid>>8 (96 dims each), partials in smem.
#define CS_SS   0                      // 16*194 = 3104
#define CS_W    3104                   // 2*3072
#define CS_K    (CS_W + 6144)
#define CS_Q    (CS_K + 6144)
#define CS_N    (CS_Q + 6144)          // 2*256
#define CS_G    (CS_N + 512)
#define CS_V    (CS_G + 512)
#define CS_A    (CS_V + 512)           // 2*192
#define CS_X    (CS_A + 384)
#define CS_U    (CS_X + 256)
#define CS_PY   (CS_U + 256)           // 2*256 partial Y
#define CS_PO   (CS_PY + 512)          // 2*256 partial O
#define CS_TOTF (CS_PO + 512)
#define CS_BYTES (CS_TOTF * 4)

__global__ __launch_bounds__(512)
void chunk_seq(const float* __restrict__ wg, const float* __restrict__ kg,
               const float* __restrict__ qg, const float* __restrict__ a16g,
               const float* __restrict__ Ng, const float* __restrict__ Gg,
               const float* __restrict__ kvb, float* __restrict__ o) {
    extern __shared__ float dyn[];
    const int h     = blockIdx.x >> 3;
    const int vbase = (blockIdx.x & 7) * 16;
    const int tid   = threadIdx.x;
    const int half  = tid >> 8;       // 0/1: d-range split
    const int r     = tid & 255;
    const int t     = r >> 4;         // 0..15
    const int j     = r & 15;         // 0..15

    float* Ss = dyn + CS_SS;
    float* Xs = dyn + CS_X;
    float* Us = dyn + CS_U;
    float* PY = dyn + CS_PY;
    float* PO = dyn + CS_PO;

    for (int i = tid; i < 16 * 194; i += 512) Ss[i] = 0.f;

    #define CS_ISSUE(cc, b) do {                                                      \
        const int _ch = (cc) * 8 + h;                                                 \
        float* wB2 = dyn + CS_W + (b) * 3072;                                         \
        float* kB2 = dyn + CS_K + (b) * 3072;                                         \
        float* qB2 = dyn + CS_Q + (b) * 3072;                                         \
        const long gb = (long)_ch * 3072;                                             \
        for (int i = tid * 4; i < 3072; i += 2048) {                                  \
            cp16(wB2 + i, wg + gb + i);                                               \
            cp16(kB2 + i, kg + gb + i);                                               \
            cp16(qB2 + i, qg + gb + i);                                               \
        }                                                                             \
        if (tid < 64)        cp16(dyn + CS_N + (b) * 256 + tid * 4,                   \
                                  Ng + (long)_ch * 256 + tid * 4);                    \
        else if (tid < 128) { int u2 = tid - 64;                                      \
                              cp16(dyn + CS_G + (b) * 256 + u2 * 4,                   \
                                   Gg + (long)_ch * 256 + u2 * 4); }                  \
        else if (tid < 176) { int u2 = tid - 128;                                     \
                              cp16(dyn + CS_A + (b) * 192 + u2 * 4,                   \
                                   a16g + (long)_ch * 192 + u2 * 4); }                \
        else if (tid < 240) { int u2 = tid - 176; int tt = u2 >> 2, pp = u2 & 3;      \
                              cp16(dyn + CS_V + (b) * 256 + tt * 16 + pp * 4,         \
                                   kvb + (long)((cc) * 16 + tt) * 2048 + h * 256 + 128\
                                   + vbase + pp * 4); }                               \
        CP_COMMIT();                                                                  \
    } while (0)

    CS_ISSUE(0, 0);
    CP_WAIT0();
    __syncthreads();

    for (int c = 0; c < NCH; ++c) {
        const int cur = c & 1;
        if (c + 1 < NCH) CS_ISSUE(c + 1, cur ^ 1);

        const float* wB = dyn + CS_W + cur * 3072;
        const float* kB = dyn + CS_K + cur * 3072;
        const float* qB = dyn + CS_Q + cur * 3072;
        const float* NB = dyn + CS_N + cur * 256;
        const float* GB = dyn + CS_G + cur * 256;
        const float* VB = dyn + CS_V + cur * 256;
        const float* AB = dyn + CS_A + cur * 192;

        // ---- partial Y0/Opart over this half's 96 dims ----
        const float* wrow = wB + t * 192 + half * 96;
        const float* qrow = qB + t * 192 + half * 96;
        const float* srow = Ss + j * 194 + half * 96;
        float y0 = 0.f, y1 = 0.f, y2 = 0.f, y3 = 0.f;
        float p0 = 0.f, p1 = 0.f, p2 = 0.f, p3 = 0.f;
        #pragma unroll
        for (int d = 0; d < 96; d += 4) {
            float4 w4 = *(const float4*)(wrow + d);
            float4 q4 = *(const float4*)(qrow + d);
            float2 sa = *(const float2*)(srow + d);
            float2 sb = *(const float2*)(srow + d + 2);
            y0 = fmaf(w4.x, sa.x, y0); y1 = fmaf(w4.y, sa.y, y1);
            y2 = fmaf(w4.z, sb.x, y2); y3 = fmaf(w4.w, sb.y, y3);
            p0 = fmaf(q4.x, sa.x, p0); p1 = fmaf(q4.y, sa.y, p1);
            p2 = fmaf(q4.z, sb.x, p2); p3 = fmaf(q4.w, sb.y, p3);
        }
        PY[half * 256 + r] = (y0 + y1) + (y2 + y3);
        PO[half * 256 + r] = (p0 + p1) + (p2 + p3);
        __syncthreads();

        // ---- X = V - Y ----
        if (half == 0)
            Xs[r] = VB[r] - (PY[r] + PY[256 + r]);
        __syncthreads();

        // ---- U = N X ----
        if (half == 0) {
            float u = 0.f;
            #pragma unroll
            for (int s = 0; s < CC; ++s)
                u = fmaf(NB[t * 16 + s], Xs[s * 16 + j], u);
            Us[r] = u;
        }
        __syncthreads();

        if (half == 0) {
            // ---- O = Opart + G U; write ----
            float ov = PO[r] + PO[256 + r];
            #pragma unroll
            for (int s = 0; s < CC; ++s)
                ov = fmaf(GB[t * 16 + s], Us[s * 16 + j], ov);
            if (ov != ov) ov = 0.f;
            ov = fminf(fmaxf(ov, -10000.f), 10000.f);
            o[(long)(c * CC + t) * 1024 + h * 128 + vbase + j] = ov;

            // ---- S[j][d] = a(d)*(S[j][d] + sum_s kappa[s][d] U[s][j]), d = t*12..+11 ----
            float ur[CC];
            #pragma unroll
            for (int s = 0; s < CC; ++s) ur[s] = Us[s * 16 + j];
            float* sr = Ss + j * 194 + t * 12;
            float sreg[12];
            #pragma unroll
            for (int i2 = 0; i2 < 12; i2 += 2) {
                float2 tmp = *(const float2*)(sr + i2);
                sreg[i2] = tmp.x; sreg[i2 + 1] = tmp.y;
            }
            const float* kp = kB + t * 12;
            #pragma unroll
            for (int s = 0; s < CC; ++s) {
                const float* krow = kp + s * 192;
                float4 k0 = *(const float4*)(krow);
                float4 k1 = *(const float4*)(krow + 4);
                float4 k2 = *(const float4*)(krow + 8);
                const float us = ur[s];
                sreg[0] = fmaf(k0.x, us, sreg[0]);  sreg[1] = fmaf(k0.y, us, sreg[1]);
                sreg[2] = fmaf(k0.z, us, sreg[2]);  sreg[3] = fmaf(k0.w, us, sreg[3]);
                sreg[4] = fmaf(k1.x, us, sreg[4]);  sreg[5] = fmaf(k1.y, us, sreg[5]);
                sreg[6] = fmaf(k1.z, us, sreg[6]);  sreg[7] = fmaf(k1.w, us, sreg[7]);
                sreg[8] = fmaf(k2.x, us, sreg[8]);  sreg[9] = fmaf(k2.y, us, sreg[9]);
                sreg[10] = fmaf(k2.z, us, sreg[10]); sreg[11] = fmaf(k2.w, us, sreg[11]);
            }
            const float* ap = AB + t * 12;
            #pragma unroll
            for (int i2 = 0; i2 < 12; i2 += 2) {
                float2 tmp;
                tmp.x = sreg[i2] * ap[i2];
                tmp.y = sreg[i2 + 1] * ap[i2 + 1];
                *(float2*)(sr + i2) = tmp;
            }
        }
        CP_WAIT0();
        __syncthreads();
    }
    #undef CS_ISSUE
}

// ---------------- launch ----------------
extern "C" void kernel_launch(void* const* d_in, const int* in_sizes, int n_in,
                              void* d_out, int out_size) {
    (void)in_sizes; (void)n_in; (void)out_size;
    const float* x         = (const float*)d_in[0];
    const float* wq_a      = (const float*)d_in[3];
    const float* q_norm_w  = (const float*)d_in[4];
    const float* wq_b      = (const float*)d_in[5];
    const float* wkv_a     = (const float*)d_in[6];
    const float* kv_norm_w = (const float*)d_in[7];
    const float* wkv_b     = (const float*)d_in[8];
    const float* wg_w      = (const float*)d_in[9];
    const float* wg_b      = (const float*)d_in[10];
    const float* wb        = (const float*)d_in[11];
    const float* wo        = (const float*)d_in[12];
    float* out = (float*)d_out;

    float *bc, *big, *qn, *kvn, *q, *kv, *kf, *ov;
    float *wch, *kch, *qch, *a16, *Nm, *Gm;
    cudaGetSymbolAddress((void**)&bc,  d_bc);
    cudaGetSymbolAddress((void**)&big, d_big);
    cudaGetSymbolAddress((void**)&qn,  d_qn);
    cudaGetSymbolAddress((void**)&kvn, d_kvn);
    cudaGetSymbolAddress((void**)&q,   d_q);
    cudaGetSymbolAddress((void**)&kv,  d_kv);
    cudaGetSymbolAddress((void**)&kf,  d_kf);
    cudaGetSymbolAddress((void**)&ov,  d_ov);
    cudaGetSymbolAddress((void**)&wch, d_wch);
    cudaGetSymbolAddress((void**)&kch, d_kch);
    cudaGetSymbolAddress((void**)&qch, d_qch);
    cudaGetSymbolAddress((void**)&a16, d_a16);
    cudaGetSymbolAddress((void**)&Nm,  d_Nm);
    cudaGetSymbolAddress((void**)&Gm,  d_Gm);

    static int smem_set = 0;
    if (!smem_set) {
        cudaFuncSetAttribute(chunk_seq, cudaFuncAttributeMaxDynamicSharedMemorySize, CS_BYTES);
        smem_set = 1;
    }

    concat_w<<<dim3(NBIG / 128, DIMX), 128>>>(wq_a, wkv_a, wg_w, wb, bc);

    // Stage 1: big = x @ [wq_a | wkv_a | wg_w | wb] (+ sigmoid epilogues)
    tgemm_kernel<1><<<dim3(NBIG / BN, TT / BM), 256>>>(NBIG, DIMX, x, DIMX, bc, NBIG, wg_b, big, NBIG);

    // Stage 2: fused RMS norms
    rms_fused<<<TT, 256>>>(big, q_norm_w, kv_norm_w, qn, kvn);

    // Stage 3: batched up-projections
    tgemm_dual_kernel<<<dim3(2048 / BN, TT / BM, 2), 256>>>(
        1536, QLR,  qn,  wq_b,  q,
        2048, KVLR, kvn, wkv_b, kv);

    // Stage 4: l2norm q/k, assemble k
    prep_kernel<<<TT * HH, 192>>>(q, kv, big, kf);

    // Stage 5a: chunk prepass
    chunk_pre<<<NCH * HH, 256>>>(q, kf, big, wch, kch, qch, a16, Nm, Gm);

    // Stage 5b: sequential chunk scan (512 threads, d-split halves)
    chunk_seq<<<HH * 8, 512, CS_BYTES>>>(wch, kch, qch, a16, Nm, Gm, kv, ov);

    // Stage 6: output projection (plain TF32)
    tgemm_kernel<0><<<dim3(DIMX / BN, TT / BM), 256>>>(DIMX, DIMX, ov, DIMX, wo, DIMX, nullptr, out, DIMX);
}